// round 13
// baseline (speedup 1.0000x reference)
#include <cuda_runtime.h>
#include <cuda_bf16.h>
#include <math.h>
#include <cstdint>

// Shapes (fixed)
#define DIMN   1024
#define BB     2
#define TT     512
#define HH     8
#define HKD    128
#define NROWS  (BB*TT)          // 1024
#define CH     64               // chunk length
#define NC     (TT/CH)          // 8 chunks
#define QSCALE 0.08838834764831845f   // 128^-0.5
#define GNORM  0.0625f                // 1/16

// ---------------------------------------------------------------------------
// Scratch (no cudaMalloc allowed)
// ---------------------------------------------------------------------------
__device__ float g_q [NROWS*DIMN];
__device__ float g_k [NROWS*DIMN];
__device__ float g_v [NROWS*DIMN];
__device__ float g_g [NROWS*DIMN];
__device__ float g_gk[NROWS*DIMN];
// chunked-GLA scratch
__device__ float g_qg[NROWS*DIMN];
__device__ float g_kd[NROWS*DIMN];
__device__ float g_kv[16*NC*HKD*HKD];
__device__ float g_S [16*NC*HKD*HKD];
__device__ float g_dc[16*NC*HKD];
// bf16 split-precision operands
__device__ __nv_bfloat16 g_xhi [NROWS*DIMN];
__device__ __nv_bfloat16 g_xlo [NROWS*DIMN];
__device__ __nv_bfloat16 g_onhi[NROWS*DIMN];
__device__ __nv_bfloat16 g_onlo[NROWS*DIMN];
__device__ __nv_bfloat16 g_Whi [5*DIMN*DIMN];   // transposed: [n][k]
__device__ __nv_bfloat16 g_Wlo [5*DIMN*DIMN];

// ---------------------------------------------------------------------------
// PTX helpers (all non-'a'-gated: cp.async / ldmatrix / mma.sync)
// ---------------------------------------------------------------------------
__device__ __forceinline__ uint32_t smem_u32(const void* p) {
    uint32_t a;
    asm("{ .reg .u64 t; cvta.to.shared.u64 t, %1; cvt.u32.u64 %0, t; }"
        : "=r"(a) : "l"(p));
    return a;
}
__device__ __forceinline__ void cp16(uint32_t dst, const void* src) {
    asm volatile("cp.async.cg.shared.global [%0], [%1], 16;"
                 :: "r"(dst), "l"(src) : "memory");
}
__device__ __forceinline__ void cp_commit() {
    asm volatile("cp.async.commit_group;" ::: "memory");
}
__device__ __forceinline__ void ldsm4(uint32_t& r0, uint32_t& r1,
                                      uint32_t& r2, uint32_t& r3, uint32_t a) {
    asm volatile("ldmatrix.sync.aligned.m8n8.x4.shared.b16 {%0,%1,%2,%3}, [%4];"
                 : "=r"(r0), "=r"(r1), "=r"(r2), "=r"(r3) : "r"(a));
}
__device__ __forceinline__ void mma16816(float* c, const uint32_t* a,
                                         const uint32_t* b) {
    asm volatile("mma.sync.aligned.m16n8k16.row.col.f32.bf16.bf16.f32 "
        "{%0,%1,%2,%3}, {%4,%5,%6,%7}, {%8,%9}, {%0,%1,%2,%3};"
        : "+f"(c[0]), "+f"(c[1]), "+f"(c[2]), "+f"(c[3])
        : "r"(a[0]), "r"(a[1]), "r"(a[2]), "r"(a[3]), "r"(b[0]), "r"(b[1]));
}

__device__ __forceinline__ void split_bf16(float x, __nv_bfloat16& h, __nv_bfloat16& l) {
    h = __float2bfloat16(x);
    l = __float2bfloat16(x - __bfloat162float(h));
}

// ---------------------------------------------------------------------------
// Prelude: lowrank_gk (64 blocks, FIRST: heaviest) + conv_x (1024) + conv_w
// (5120). Device globals referenced INSIDE (ATS shadow pitfall).
// ---------------------------------------------------------------------------
__global__ __launch_bounds__(256) void prelude_kernel(
    const float* __restrict__ x,
    const float* __restrict__ Wq, const float* __restrict__ Wk,
    const float* __restrict__ Wv, const float* __restrict__ Wg,
    const float* __restrict__ Wo,
    const float* __restrict__ Wgk1, const float* __restrict__ Wgk2,
    const float* __restrict__ bgk2)
{
    __shared__ float sbuf[5376];
    const int bid = blockIdx.x;
    const int tid = threadIdx.x;

    if (bid < 64) {
        // ---- lowrank_gk: 16 rows per block ----
        const int m0 = bid * 16;
        float (*sX)[64]        = (float(*)[64])sbuf;
        float (*sPart)[16][16] = (float(*)[16][16])(sbuf + 1024);
        float (*sT1)[16]       = (float(*)[16])(sbuf + 5120);

        const int kk = tid >> 4;
        const int cc = tid & 15;

        float acc16[16];
#pragma unroll
        for (int r = 0; r < 16; r++) acc16[r] = 0.f;

        for (int kc = 0; kc < 16; kc++) {
            {
                int row = tid >> 4, c4 = (tid & 15) << 2;
                *(float4*)&sX[row][c4] =
                    *(const float4*)(x + (size_t)(m0 + row) * DIMN + kc * 64 + c4);
            }
            __syncthreads();
#pragma unroll
            for (int i = 0; i < 4; i++) {
                int k = kk * 4 + i;
                float w1 = Wgk1[(kc * 64 + k) * 16 + cc];
#pragma unroll
                for (int r = 0; r < 16; r++)
                    acc16[r] = fmaf(sX[r][k], w1, acc16[r]);
            }
            __syncthreads();
        }
#pragma unroll
        for (int r = 0; r < 16; r++) sPart[kk][r][cc] = acc16[r];
        __syncthreads();
        {
            int rr = tid >> 4;
            float s = 0.f;
#pragma unroll
            for (int j = 0; j < 16; j++) s += sPart[j][rr][cc];
            sT1[rr][cc] = s;
        }
        __syncthreads();
#pragma unroll
        for (int u = 0; u < 4; u++) {
            int n = u * 256 + tid;
            float w2[16];
#pragma unroll
            for (int j = 0; j < 16; j++) w2[j] = Wgk2[j * DIMN + n];
            float bias = bgk2[n];
#pragma unroll
            for (int r = 0; r < 16; r++) {
                float a = bias;
#pragma unroll
                for (int j = 0; j < 16; j++)
                    a = fmaf(sT1[r][j], w2[j], a);
                float ls = fminf(a, 0.f) - log1pf(__expf(-fabsf(a)));
                g_gk[(size_t)(m0 + r) * DIMN + n] = ls * GNORM;
            }
        }
    } else if (bid < 1088) {
        // ---- conv_x: x fp32 -> bf16 hi/lo ----
        int i = (bid - 64) * 256 + tid;       // float4 index
        float4 v = ((const float4*)x)[i];
        __nv_bfloat16 h[4], l[4];
        split_bf16(v.x, h[0], l[0]); split_bf16(v.y, h[1], l[1]);
        split_bf16(v.z, h[2], l[2]); split_bf16(v.w, h[3], l[3]);
        __nv_bfloat162* ph = (__nv_bfloat162*)g_xhi;
        __nv_bfloat162* pl = (__nv_bfloat162*)g_xlo;
        ph[i*2]   = __nv_bfloat162(h[0], h[1]);
        ph[i*2+1] = __nv_bfloat162(h[2], h[3]);
        pl[i*2]   = __nv_bfloat162(l[0], l[1]);
        pl[i*2+1] = __nv_bfloat162(l[2], l[3]);
    } else {
        // ---- conv_w: W fp32 [k][n] -> transposed bf16 hi/lo [n][k] ----
        const float* Ws[5] = {Wq, Wk, Wv, Wg, Wo};
        const int rr  = bid - 1088;
        const int z   = rr >> 10;
        const int rem = rr & 1023;
        const int kt0 = (rem >> 5) * 32;
        const int nt0 = (rem & 31) * 32;
        const float* W = Ws[z];
        __nv_bfloat16* Dhi = g_Whi + (size_t)z * DIMN * DIMN;
        __nv_bfloat16* Dlo = g_Wlo + (size_t)z * DIMN * DIMN;

        float (*s)[33] = (float(*)[33])sbuf;
        int tx = tid & 31, ty = tid >> 5;
#pragma unroll
        for (int j = 0; j < 4; j++)
            s[ty + j*8][tx] = W[(kt0 + ty + j*8) * DIMN + nt0 + tx];
        __syncthreads();
#pragma unroll
        for (int j = 0; j < 4; j++) {
            int n = nt0 + ty + j*8, k = kt0 + tx;
            float w = s[tx][ty + j*8];
            __nv_bfloat16 h, l; split_bf16(w, h, l);
            Dhi[(size_t)n * DIMN + k] = h;
            Dlo[(size_t)n * DIMN + k] = l;
        }
    }
}

// ---------------------------------------------------------------------------
// HMMA split-3 GEMM, templated on BN (64 for gemm4, 32 for gemmo).
// Block tile 128xBN, BK=32, 8 warps (4m x 2n), 3-stage cp.async +
// register fragment double-buffering, 1 sync per K-step.
// ---------------------------------------------------------------------------
#define O_AHI 0
#define O_ALO 8192
#define O_BHI 16384

template<int BN> struct GemmCfg {
    static constexpr int STG   = 16384 + BN * 128;   // stage bytes
    static constexpr int NT    = BN / 16;            // n-subtiles per warp
    static constexpr int O_BLO = 16384 + BN * 64;
};

__device__ __forceinline__ uint32_t sw_addr(uint32_t region, int row, int chunk) {
    return region + row * 64 + ((chunk ^ ((row >> 1) & 3)) << 4);
}

template<int BN>
__device__ __forceinline__ void load_stageT(
    uint32_t sb, int s,
    const __nv_bfloat16* __restrict__ Ahi, const __nv_bfloat16* __restrict__ Alo,
    const __nv_bfloat16* __restrict__ Bhi, const __nv_bfloat16* __restrict__ Blo,
    int m0, int n0, int k0, int tid)
{
    uint32_t st = sb + s * GemmCfg<BN>::STG;
#pragma unroll
    for (int i = 0; i < 2; i++) {
        int idx = tid + (i << 8);          // 0..511
        int row = idx >> 2, c = idx & 3;
        const size_t go = (size_t)(m0 + row) * DIMN + k0 + c * 8;
        cp16(sw_addr(st + O_AHI, row, c), Ahi + go);
        cp16(sw_addr(st + O_ALO, row, c), Alo + go);
    }
    if (BN == 64) {
        int row = tid >> 2, c = tid & 3;   // 64 rows x 4 chunks
        const size_t go = (size_t)(n0 + row) * DIMN + k0 + c * 8;
        cp16(sw_addr(st + O_BHI, row, c), Bhi + go);
        cp16(sw_addr(st + GemmCfg<BN>::O_BLO, row, c), Blo + go);
    } else {
        if (tid < BN * 4) {
            int row = tid >> 2, c = tid & 3;
            const size_t go = (size_t)(n0 + row) * DIMN + k0 + c * 8;
            cp16(sw_addr(st + O_BHI, row, c), Bhi + go);
            cp16(sw_addr(st + GemmCfg<BN>::O_BLO, row, c), Blo + go);
        }
    }
    cp_commit();
}

template<int NT> struct FragSetT {
    uint32_t ahi[2][4], alo[2][4];
    uint32_t bhi[NT][2], blo[NT][2];
};

template<int BN>
__device__ __forceinline__ void ld_fragsT(FragSetT<GemmCfg<BN>::NT>& f,
                                          uint32_t st, int ch,
                                          int wm0, int wn0, int lr)
{
#pragma unroll
    for (int mt = 0; mt < 2; mt++) {
        int row = wm0 + mt * 16 + lr;
        ldsm4(f.ahi[mt][0], f.ahi[mt][1], f.ahi[mt][2], f.ahi[mt][3],
              sw_addr(st + O_AHI, row, ch));
        ldsm4(f.alo[mt][0], f.alo[mt][1], f.alo[mt][2], f.alo[mt][3],
              sw_addr(st + O_ALO, row, ch));
    }
#pragma unroll
    for (int ng = 0; ng < GemmCfg<BN>::NT / 2; ng++) {
        int row = wn0 + ng * 16 + lr;
        uint32_t t0, t1, t2, t3;
        ldsm4(t0, t1, t2, t3, sw_addr(st + O_BHI, row, ch));
        f.bhi[ng*2][0] = t0; f.bhi[ng*2+1][0] = t1;
        f.bhi[ng*2][1] = t2; f.bhi[ng*2+1][1] = t3;
        ldsm4(t0, t1, t2, t3, sw_addr(st + GemmCfg<BN>::O_BLO, row, ch));
        f.blo[ng*2][0] = t0; f.blo[ng*2+1][0] = t1;
        f.blo[ng*2][1] = t2; f.blo[ng*2+1][1] = t3;
    }
}

template<int BN>
__device__ __forceinline__ void mma_setT(float acc[2][GemmCfg<BN>::NT][4],
                                         const FragSetT<GemmCfg<BN>::NT>& f)
{
#pragma unroll
    for (int mt = 0; mt < 2; mt++)
#pragma unroll
        for (int nt = 0; nt < GemmCfg<BN>::NT; nt++) {
            mma16816(acc[mt][nt], f.ahi[mt], f.bhi[nt]);
            mma16816(acc[mt][nt], f.ahi[mt], f.blo[nt]);
            mma16816(acc[mt][nt], f.alo[mt], f.bhi[nt]);
        }
}

template<int BN>
__device__ __forceinline__ void gemm_bodyT(
    const __nv_bfloat16* __restrict__ Ahi, const __nv_bfloat16* __restrict__ Alo,
    const __nv_bfloat16* __restrict__ Bhi, const __nv_bfloat16* __restrict__ Blo,
    float* __restrict__ C, float alpha, char* smem)
{
    constexpr int NT = GemmCfg<BN>::NT;
    const int tid  = threadIdx.x;
    const int wid  = tid >> 5;
    const int lane = tid & 31;
    const int m0 = blockIdx.y * 128;
    const int n0 = blockIdx.x * BN;
    const int wm0 = (wid & 3) * 32;
    const int wn0 = (wid >> 2) * (BN / 2);
    const uint32_t sb = smem_u32(smem);

    float acc[2][NT][4];
#pragma unroll
    for (int mt = 0; mt < 2; mt++)
#pragma unroll
        for (int nt = 0; nt < NT; nt++)
#pragma unroll
            for (int i = 0; i < 4; i++) acc[mt][nt][i] = 0.f;

    load_stageT<BN>(sb, 0, Ahi, Alo, Bhi, Blo, m0, n0, 0,  tid);
    load_stageT<BN>(sb, 1, Ahi, Alo, Bhi, Blo, m0, n0, 32, tid);

    const int lr = lane & 15;
    const int lc = lane >> 4;

    asm volatile("cp.async.wait_group 1;" ::: "memory");
    __syncthreads();

    FragSetT<NT> cur, nxt;
    int stage = 0;
    uint32_t st = sb;
    ld_fragsT<BN>(cur, st, lc, wm0, wn0, lr);

    for (int kt = 0; kt < 32; kt++) {
        ld_fragsT<BN>(nxt, st, 2 + lc, wm0, wn0, lr);
        mma_setT<BN>(acc, cur);
        if (kt < 31) {
            if (kt < 30) {
                int ns = stage + 2; if (ns >= 3) ns -= 3;
                load_stageT<BN>(sb, ns, Ahi, Alo, Bhi, Blo, m0, n0,
                                (kt + 2) * 32, tid);
                asm volatile("cp.async.wait_group 1;" ::: "memory");
            } else {
                asm volatile("cp.async.wait_group 0;" ::: "memory");
            }
            __syncthreads();
            stage++; if (stage == 3) stage = 0;
            st = sb + stage * GemmCfg<BN>::STG;
            ld_fragsT<BN>(cur, st, lc, wm0, wn0, lr);
        }
        mma_setT<BN>(acc, nxt);
    }

    const int er = lane >> 2;
    const int ec = (lane & 3) << 1;
#pragma unroll
    for (int mt = 0; mt < 2; mt++)
#pragma unroll
        for (int nt = 0; nt < NT; nt++) {
            int row = m0 + wm0 + mt * 16 + er;
            int col = n0 + wn0 + nt * 8 + ec;
            float2 v0 = make_float2(acc[mt][nt][0] * alpha, acc[mt][nt][1] * alpha);
            float2 v1 = make_float2(acc[mt][nt][2] * alpha, acc[mt][nt][3] * alpha);
            *(float2*)(C + (size_t)row * DIMN + col)       = v0;
            *(float2*)(C + (size_t)(row + 8) * DIMN + col) = v1;
        }
}

#define SMEM_GEMM4 (3 * GemmCfg<64>::STG)    // 73728
#define SMEM_GEMMO (3 * GemmCfg<32>::STG)    // 61440

__global__ __launch_bounds__(256, 2) void gemm4_kernel()
{
    extern __shared__ char smem[];
    const int z = blockIdx.z;
    const __nv_bfloat16* Bhi = g_Whi + (size_t)z * DIMN * DIMN;
    const __nv_bfloat16* Blo = g_Wlo + (size_t)z * DIMN * DIMN;
    float* outs[4] = {g_q, g_k, g_v, g_g};
    float alpha = (z == 0) ? QSCALE : 1.f;
    gemm_bodyT<64>(g_xhi, g_xlo, Bhi, Blo, outs[z], alpha, smem);
}

__global__ __launch_bounds__(256, 2) void gemmo_kernel(float* __restrict__ out)
{
    extern __shared__ char smem[];
    gemm_bodyT<32>(g_onhi, g_onlo, g_Whi + (size_t)4 * DIMN * DIMN,
                   g_Wlo + (size_t)4 * DIMN * DIMN, out, 1.f, smem);
}

// ---------------------------------------------------------------------------
// Chunked GLA
// ---------------------------------------------------------------------------
__device__ __forceinline__ int row_off(int b, int h, int t)
{
    return (((b * TT + t) * HH + h) << 7);
}

// Fused prep + chunk_kv, v-split into 2 halves (round-12 proven).
__global__ __launch_bounds__(512) void prep_kv_kernel()
{
    const int bid = blockIdx.x;
    const int bhc = bid >> 1, vh = bid & 1;
    const int bh  = bhc >> 3, c0 = bhc & 7;
    const int b   = bh >> 3,  h  = bh & 7;
    const int tid = threadIdx.x;
    const int ch  = tid & 127;
    const int tg  = tid >> 7;
    const int tb  = c0 * CH + tg * 16;

    __shared__ float gsum[4][128];
    __shared__ float sK[64][128];
    __shared__ float sV[16][64];

    float loc[16];
    {
        float a = 0.f;
#pragma unroll
        for (int s = 0; s < 16; s++) {
            loc[s] = g_gk[row_off(b, h, tb + s) + ch];
            a += loc[s];
        }
        gsum[tg][ch] = a;
    }
    __syncthreads();
    {
        float off = 0.f;
#pragma unroll
        for (int g = 0; g < 4; g++)
            if (g < tg) off += gsum[g][ch];
        float tot = gsum[0][ch] + gsum[1][ch] + gsum[2][ch] + gsum[3][ch];
        float bacc = off;
#pragma unroll 4
        for (int s = 0; s < 16; s++) {
            bacc += loc[s];
            int r = row_off(b, h, tb + s) + ch;
            float q = g_q[r], k = g_k[r];
            if (vh == 0) {
                g_qg[r] = q * __expf(bacc);
                g_kd[r] = k * __expf(-bacc);
            }
            sK[tg * 16 + s][ch] = k * __expf(tot - bacc);
        }
        if (vh == 0 && tg == 0) g_dc[bhc * 128 + ch] = __expf(tot);
    }
    __syncthreads();

    const int tr  = tid >> 4, tc = tid & 15;
    const int kr0 = tr << 2, vc0 = tc << 2;
    const int tbase = c0 * CH;
    const int vbase = vh * 64;

    float acc[4][4];
#pragma unroll
    for (int i = 0; i < 4; i++)
#pragma unroll
        for (int j = 0; j < 4; j++) acc[i][j] = 0.f;

    for (int st = 0; st < 4; st++) {
        if (tid < 256) {
            int sr = tid >> 4;
            int sc = (tid & 15) << 2;
            int r  = row_off(b, h, tbase + st * 16 + sr) + vbase + sc;
            *(float4*)&sV[sr][sc] = *(const float4*)(g_v + r);
        }
        __syncthreads();
#pragma unroll
        for (int ss = 0; ss < 16; ss++) {
            int s = st * 16 + ss;
            float4 k4 = *(const float4*)&sK[s][kr0];
            float4 v4 = *(const float4*)&sV[ss][vc0];
            float kr[4] = {k4.x,k4.y,k4.z,k4.w};
            float vr[4] = {v4.x,v4.y,v4.z,v4.w};
#pragma unroll
            for (int i = 0; i < 4; i++)
#pragma unroll
                for (int j = 0; j < 4; j++)
                    acc[i][j] = fmaf(kr[i], vr[j], acc[i][j]);
        }
        __syncthreads();
    }

    float* dst = g_kv + (size_t)bhc * 16384 + vbase;
#pragma unroll
    for (int i = 0; i < 4; i++)
        *(float4*)(dst + (kr0 + i) * 128 + vc0) =
            make_float4(acc[i][0], acc[i][1], acc[i][2], acc[i][3]);
}

// state scan v2 (round-12 proven)
__global__ __launch_bounds__(256) void state_scan_kernel()
{
    const int bh = blockIdx.x >> 4;
    const int vg = blockIdx.x & 15;
    const int tid = threadIdx.x;
    const int k  = tid >> 1;
    const int v0 = vg * 8 + (tid & 1) * 4;

    const size_t slab = (size_t)bh * NC * 16384 + (size_t)k * 128 + v0;
    const int dbase = bh * NC * 128 + k;

    float4 S = make_float4(0.f, 0.f, 0.f, 0.f);
    float4 kv = *(const float4*)(g_kv + slab);
    float  d  = g_dc[dbase];

    for (int c = 0; c < NC; c++) {
        *(float4*)(g_S + slab + (size_t)c * 16384) = S;
        S.x = fmaf(S.x, d, kv.x); S.y = fmaf(S.y, d, kv.y);
        S.z = fmaf(S.z, d, kv.z); S.w = fmaf(S.w, d, kv.w);
        if (c < NC - 1) {
            kv = *(const float4*)(g_kv + slab + (size_t)(c + 1) * 16384);
            d  = g_dc[dbase + (c + 1) * 128];
        }
    }
}

// chunk_out v2: t-split into 2 halves of 32 rows -> 256 blocks.
// 8 warps x 4 t-rows; lane owns 4 v-cols; full-warp shuffle RMS.
__global__ __launch_bounds__(256) void chunk_out_kernel(
    const float* __restrict__ g_norm_w)
{
    const int bid = blockIdx.x;
    const int bhc = bid >> 1, th = bid & 1;
    const int bh  = bhc >> 3, c0 = bhc & 7;
    const int b   = bh >> 3,  h  = bh & 7;
    const int tid = threadIdx.x;
    const int wr  = tid >> 5;          // 0..7
    const int lane = tid & 31;
    const int t0  = wr << 2;           // local t base within half (0..28)
    const int v0  = lane << 2;         // 0..124
    const int tchunk = c0 * CH;
    const int tbase  = tchunk + th * 32;

    __shared__ float sQ [16][34];      // [k][t_local 32]
    __shared__ float sKd[16][68];      // [k][s 64]
    __shared__ float sS [16][128];
    __shared__ float sA [32][68];
    __shared__ float sV [16][128];

    float o[4][4];
    float a2[4][2];
#pragma unroll
    for (int i = 0; i < 4; i++) {
#pragma unroll
        for (int j = 0; j < 4; j++) o[i][j] = 0.f;
        a2[i][0] = 0.f; a2[i][1] = 0.f;
    }

    const size_t Sbase = (size_t)bhc * 16384;

    for (int k0 = 0; k0 < 128; k0 += 16) {
        {   // stage q~ for this half's 32 t-rows (transposed)
            int tl = tid >> 3;
            int k2 = (tid & 7) << 1;
            int r  = row_off(b, h, tbase + tl) + k0 + k2;
            float2 qv = *(const float2*)(g_qg + r);
            sQ[k2][tl] = qv.x; sQ[k2+1][tl] = qv.y;
        }
        {   // stage k^ for the FULL chunk's 64 s-rows (transposed)
            int sl = tid >> 2;
            int c4 = (tid & 3) << 2;
            int r  = row_off(b, h, tchunk + sl) + k0 + c4;
            float4 kv = *(const float4*)(g_kd + r);
            sKd[c4][sl] = kv.x; sKd[c4+1][sl] = kv.y;
            sKd[c4+2][sl] = kv.z; sKd[c4+3][sl] = kv.w;
        }
#pragma unroll
        for (int u = 0; u < 2; u++) {
            int f  = tid + (u << 8);
            int sr = f >> 5;
            int sc = (f & 31) << 2;
            *(float4*)&sS[sr][sc] =
                *(const float4*)(g_S + Sbase + (k0 + sr) * 128 + sc);
        }
        __syncthreads();

#pragma unroll
        for (int kk = 0; kk < 16; kk++) {
            float qr[4];
#pragma unroll
            for (int i = 0; i < 4; i++) qr[i] = sQ[kk][t0 + i];
            float4 s4 = *(const float4*)&sS[kk][v0];
            float kd0 = sKd[kk][lane*2], kd1 = sKd[kk][lane*2 + 1];
#pragma unroll
            for (int i = 0; i < 4; i++) {
                o[i][0] = fmaf(qr[i], s4.x, o[i][0]);
                o[i][1] = fmaf(qr[i], s4.y, o[i][1]);
                o[i][2] = fmaf(qr[i], s4.z, o[i][2]);
                o[i][3] = fmaf(qr[i], s4.w, o[i][3]);
                a2[i][0] = fmaf(qr[i], kd0, a2[i][0]);
                a2[i][1] = fmaf(qr[i], kd1, a2[i][1]);
            }
        }
        __syncthreads();
    }

    // causal mask + stash A
#pragma unroll
    for (int i = 0; i < 4; i++) {
        int tl = t0 + i;
        int tg = th * 32 + tl;
        int s0 = lane * 2;
        sA[tl][s0]     = (s0     <= tg) ? a2[i][0] : 0.f;
        sA[tl][s0 + 1] = (s0 + 1 <= tg) ? a2[i][1] : 0.f;
    }
    __syncthreads();

    // o_intra = A @ V (contraction over s = 64)
    for (int st = 0; st < 4; st++) {
#pragma unroll
        for (int u = 0; u < 2; u++) {
            int f  = tid + (u << 8);
            int sr = f >> 5;
            int sc = (f & 31) << 2;
            int r  = row_off(b, h, tchunk + st * 16 + sr) + sc;
            *(float4*)&sV[sr][sc] = *(const float4*)(g_v + r);
        }
        __syncthreads();
#pragma unroll
        for (int ss = 0; ss < 16; ss++) {
            int s = st * 16 + ss;
            float a[4];
#pragma unroll
            for (int i = 0; i < 4; i++) a[i] = sA[t0 + i][s];
            float4 v4 = *(const float4*)&sV[ss][v0];
#pragma unroll
            for (int i = 0; i < 4; i++) {
                o[i][0] = fmaf(a[i], v4.x, o[i][0]);
                o[i][1] = fmaf(a[i], v4.y, o[i][1]);
                o[i][2] = fmaf(a[i], v4.z, o[i][2]);
                o[i][3] = fmaf(a[i], v4.w, o[i][3]);
            }
        }
        __syncthreads();
    }

    // fused gated RMSNorm + bf16 hi/lo split write
    float4 w4 = *(const float4*)(g_norm_w + v0);
    float wr_[4] = {w4.x, w4.y, w4.z, w4.w};

#pragma unroll
    for (int i = 0; i < 4; i++) {
        float ss = 0.f;
#pragma unroll
        for (int j = 0; j < 4; j++) ss = fmaf(o[i][j], o[i][j], ss);
#pragma unroll
        for (int off = 16; off; off >>= 1)
            ss += __shfl_xor_sync(0xffffffffu, ss, off);
        float rms = rsqrtf(ss * (1.f / 128.f) + 1e-5f);

        int r = row_off(b, h, tbase + t0 + i);
        float4 g4 = *(const float4*)(g_g + r + v0);
        float gr[4] = {g4.x, g4.y, g4.z, g4.w};

        union { __nv_bfloat16 h[4]; uint2 u; } hh;
        union { __nv_bfloat16 h[4]; uint2 u; } ll;
#pragma unroll
        for (int j = 0; j < 4; j++) {
            float gvv = gr[j];
            float sw  = gvv / (1.f + __expf(-gvv));
            float on  = o[i][j] * rms * wr_[j] * sw;
            split_bf16(on, hh.h[j], ll.h[j]);
        }
        *(uint2*)&g_onhi[r + v0] = hh.u;
        *(uint2*)&g_onlo[r + v0] = ll.u;
    }
}

// ---------------------------------------------------------------------------
extern "C" void kernel_launch(void* const* d_in, const int* in_sizes, int n_in,
                              void* d_out, int out_size)
{
    const float* x        = (const float*)d_in[0];
    const float* Wq       = (const float*)d_in[1];
    const float* Wk       = (const float*)d_in[2];
    const float* Wv       = (const float*)d_in[3];
    const float* Wg       = (const float*)d_in[4];
    const float* Wgk1     = (const float*)d_in[5];
    const float* Wgk2     = (const float*)d_in[6];
    const float* bgk2     = (const float*)d_in[7];
    const float* g_norm_w = (const float*)d_in[8];
    const float* Wo       = (const float*)d_in[9];
    float* out = (float*)d_out;

    // Host-side attribute set; executed during capture, not a graph node.
    cudaFuncSetAttribute(gemm4_kernel,
        cudaFuncAttributeMaxDynamicSharedMemorySize, SMEM_GEMM4);
    cudaFuncSetAttribute(gemmo_kernel,
        cudaFuncAttributeMaxDynamicSharedMemorySize, SMEM_GEMMO);

    prelude_kernel<<<6208, 256>>>(x, Wq, Wk, Wv, Wg, Wo, Wgk1, Wgk2, bgk2);
    gemm4_kernel<<<dim3(16, 8, 4), 256, SMEM_GEMM4>>>();
    prep_kv_kernel<<<256, 512>>>();
    state_scan_kernel<<<256, 256>>>();
    chunk_out_kernel<<<256, 256>>>(g_norm_w);
    gemmo_kernel<<<dim3(32, 8), 256, SMEM_GEMMO>>>(out);
}

// round 14
// speedup vs baseline: 1.2496x; 1.2496x over previous
#include <cuda_runtime.h>
#include <cuda_bf16.h>
#include <math.h>
#include <cstdint>

// Shapes (fixed)
#define DIMN   1024
#define BB     2
#define TT     512
#define HH     8
#define HKD    128
#define NROWS  (BB*TT)          // 1024
#define CH     64               // chunk length
#define NC     (TT/CH)          // 8 chunks
#define QSCALE 0.08838834764831845f   // 128^-0.5
#define GNORM  0.0625f                // 1/16

// ---------------------------------------------------------------------------
// Scratch (no cudaMalloc allowed)
// ---------------------------------------------------------------------------
__device__ float g_q [NROWS*DIMN];
__device__ float g_k [NROWS*DIMN];
__device__ float g_v [NROWS*DIMN];
__device__ float g_g [NROWS*DIMN];
__device__ float g_gk[NROWS*DIMN];
// chunked-GLA scratch
__device__ float g_qg[NROWS*DIMN];
__device__ float g_kd[NROWS*DIMN];
__device__ float g_kv[16*NC*HKD*HKD];
__device__ float g_S [16*NC*HKD*HKD];
__device__ float g_dc[16*NC*HKD];
// bf16 split-precision operands
__device__ __nv_bfloat16 g_xhi [NROWS*DIMN];
__device__ __nv_bfloat16 g_xlo [NROWS*DIMN];
__device__ __nv_bfloat16 g_onhi[NROWS*DIMN];
__device__ __nv_bfloat16 g_onlo[NROWS*DIMN];
__device__ __nv_bfloat16 g_Whi [5*DIMN*DIMN];   // transposed: [n][k]
__device__ __nv_bfloat16 g_Wlo [5*DIMN*DIMN];

// ---------------------------------------------------------------------------
// PTX helpers (all non-'a'-gated: cp.async / ldmatrix / mma.sync)
// ---------------------------------------------------------------------------
__device__ __forceinline__ uint32_t smem_u32(const void* p) {
    uint32_t a;
    asm("{ .reg .u64 t; cvta.to.shared.u64 t, %1; cvt.u32.u64 %0, t; }"
        : "=r"(a) : "l"(p));
    return a;
}
__device__ __forceinline__ void cp16(uint32_t dst, const void* src) {
    asm volatile("cp.async.cg.shared.global [%0], [%1], 16;"
                 :: "r"(dst), "l"(src) : "memory");
}
__device__ __forceinline__ void cp_commit() {
    asm volatile("cp.async.commit_group;" ::: "memory");
}
__device__ __forceinline__ void ldsm4(uint32_t& r0, uint32_t& r1,
                                      uint32_t& r2, uint32_t& r3, uint32_t a) {
    asm volatile("ldmatrix.sync.aligned.m8n8.x4.shared.b16 {%0,%1,%2,%3}, [%4];"
                 : "=r"(r0), "=r"(r1), "=r"(r2), "=r"(r3) : "r"(a));
}
__device__ __forceinline__ void mma16816(float* c, const uint32_t* a,
                                         const uint32_t* b) {
    asm volatile("mma.sync.aligned.m16n8k16.row.col.f32.bf16.bf16.f32 "
        "{%0,%1,%2,%3}, {%4,%5,%6,%7}, {%8,%9}, {%0,%1,%2,%3};"
        : "+f"(c[0]), "+f"(c[1]), "+f"(c[2]), "+f"(c[3])
        : "r"(a[0]), "r"(a[1]), "r"(a[2]), "r"(a[3]), "r"(b[0]), "r"(b[1]));
}

__device__ __forceinline__ void split_bf16(float x, __nv_bfloat16& h, __nv_bfloat16& l) {
    h = __float2bfloat16(x);
    l = __float2bfloat16(x - __bfloat162float(h));
}

// NOTE: device globals are referenced INSIDE kernels only (host-side symbol
// would be the ATS shadow -> silent wrong-memory writes).
__global__ __launch_bounds__(256) void conv_x_kernel(const float* __restrict__ x)
{
    int i = blockIdx.x * 256 + threadIdx.x;       // float4 index
    float4 v = ((const float4*)x)[i];
    __nv_bfloat16 h[4], l[4];
    split_bf16(v.x, h[0], l[0]); split_bf16(v.y, h[1], l[1]);
    split_bf16(v.z, h[2], l[2]); split_bf16(v.w, h[3], l[3]);
    __nv_bfloat162* ph = (__nv_bfloat162*)g_xhi;
    __nv_bfloat162* pl = (__nv_bfloat162*)g_xlo;
    ph[i*2]   = __nv_bfloat162(h[0], h[1]);
    ph[i*2+1] = __nv_bfloat162(h[2], h[3]);
    pl[i*2]   = __nv_bfloat162(l[0], l[1]);
    pl[i*2+1] = __nv_bfloat162(l[2], l[3]);
}

// W fp32 [k][n] -> transposed bf16 hi/lo [n][k] (5 weights via z)
__global__ __launch_bounds__(256) void conv_w_kernel(
    const float* __restrict__ Wq, const float* __restrict__ Wk,
    const float* __restrict__ Wv, const float* __restrict__ Wg,
    const float* __restrict__ Wo)
{
    const float* Ws[5] = {Wq, Wk, Wv, Wg, Wo};
    const float* W = Ws[blockIdx.z];
    __nv_bfloat16* Dhi = g_Whi + (size_t)blockIdx.z * DIMN * DIMN;
    __nv_bfloat16* Dlo = g_Wlo + (size_t)blockIdx.z * DIMN * DIMN;

    __shared__ float s[32][33];
    int tx = threadIdx.x & 31, ty = threadIdx.x >> 5;   // 32 x 8
    int kt = blockIdx.y * 32, nt = blockIdx.x * 32;
#pragma unroll
    for (int j = 0; j < 4; j++)
        s[ty + j*8][tx] = W[(kt + ty + j*8) * DIMN + nt + tx];
    __syncthreads();
#pragma unroll
    for (int j = 0; j < 4; j++) {
        int n = nt + ty + j*8, k = kt + tx;
        float w = s[tx][ty + j*8];
        __nv_bfloat16 h, l; split_bf16(w, h, l);
        Dhi[(size_t)n * DIMN + k] = h;
        Dlo[(size_t)n * DIMN + k] = l;
    }
}

// ---------------------------------------------------------------------------
// HMMA split-3 GEMM, templated on BN (64 for gemm4, 32 for gemmo).
// Block tile 128xBN, BK=32, 8 warps (4m x 2n), 3-stage cp.async +
// register fragment double-buffering, 1 sync per K-step.
// ---------------------------------------------------------------------------
#define O_AHI 0
#define O_ALO 8192
#define O_BHI 16384

template<int BN> struct GemmCfg {
    static constexpr int STG   = 16384 + BN * 128;   // stage bytes
    static constexpr int NT    = BN / 16;            // n-subtiles per warp
    static constexpr int O_BLO = 16384 + BN * 64;
};

__device__ __forceinline__ uint32_t sw_addr(uint32_t region, int row, int chunk) {
    return region + row * 64 + ((chunk ^ ((row >> 1) & 3)) << 4);
}

template<int BN>
__device__ __forceinline__ void load_stageT(
    uint32_t sb, int s,
    const __nv_bfloat16* __restrict__ Ahi, const __nv_bfloat16* __restrict__ Alo,
    const __nv_bfloat16* __restrict__ Bhi, const __nv_bfloat16* __restrict__ Blo,
    int m0, int n0, int k0, int tid)
{
    uint32_t st = sb + s * GemmCfg<BN>::STG;
#pragma unroll
    for (int i = 0; i < 2; i++) {
        int idx = tid + (i << 8);          // 0..511
        int row = idx >> 2, c = idx & 3;
        const size_t go = (size_t)(m0 + row) * DIMN + k0 + c * 8;
        cp16(sw_addr(st + O_AHI, row, c), Ahi + go);
        cp16(sw_addr(st + O_ALO, row, c), Alo + go);
    }
    if (BN == 64) {
        int row = tid >> 2, c = tid & 3;   // 64 rows x 4 chunks
        const size_t go = (size_t)(n0 + row) * DIMN + k0 + c * 8;
        cp16(sw_addr(st + O_BHI, row, c), Bhi + go);
        cp16(sw_addr(st + GemmCfg<BN>::O_BLO, row, c), Blo + go);
    } else {
        if (tid < BN * 4) {
            int row = tid >> 2, c = tid & 3;
            const size_t go = (size_t)(n0 + row) * DIMN + k0 + c * 8;
            cp16(sw_addr(st + O_BHI, row, c), Bhi + go);
            cp16(sw_addr(st + GemmCfg<BN>::O_BLO, row, c), Blo + go);
        }
    }
    cp_commit();
}

template<int NT> struct FragSetT {
    uint32_t ahi[2][4], alo[2][4];
    uint32_t bhi[NT][2], blo[NT][2];
};

template<int BN>
__device__ __forceinline__ void ld_fragsT(FragSetT<GemmCfg<BN>::NT>& f,
                                          uint32_t st, int ch,
                                          int wm0, int wn0, int lr)
{
#pragma unroll
    for (int mt = 0; mt < 2; mt++) {
        int row = wm0 + mt * 16 + lr;
        ldsm4(f.ahi[mt][0], f.ahi[mt][1], f.ahi[mt][2], f.ahi[mt][3],
              sw_addr(st + O_AHI, row, ch));
        ldsm4(f.alo[mt][0], f.alo[mt][1], f.alo[mt][2], f.alo[mt][3],
              sw_addr(st + O_ALO, row, ch));
    }
#pragma unroll
    for (int ng = 0; ng < GemmCfg<BN>::NT / 2; ng++) {
        int row = wn0 + ng * 16 + lr;
        uint32_t t0, t1, t2, t3;
        ldsm4(t0, t1, t2, t3, sw_addr(st + O_BHI, row, ch));
        f.bhi[ng*2][0] = t0; f.bhi[ng*2+1][0] = t1;
        f.bhi[ng*2][1] = t2; f.bhi[ng*2+1][1] = t3;
        ldsm4(t0, t1, t2, t3, sw_addr(st + GemmCfg<BN>::O_BLO, row, ch));
        f.blo[ng*2][0] = t0; f.blo[ng*2+1][0] = t1;
        f.blo[ng*2][1] = t2; f.blo[ng*2+1][1] = t3;
    }
}

template<int BN>
__device__ __forceinline__ void mma_setT(float acc[2][GemmCfg<BN>::NT][4],
                                         const FragSetT<GemmCfg<BN>::NT>& f)
{
#pragma unroll
    for (int mt = 0; mt < 2; mt++)
#pragma unroll
        for (int nt = 0; nt < GemmCfg<BN>::NT; nt++) {
            mma16816(acc[mt][nt], f.ahi[mt], f.bhi[nt]);
            mma16816(acc[mt][nt], f.ahi[mt], f.blo[nt]);
            mma16816(acc[mt][nt], f.alo[mt], f.bhi[nt]);
        }
}

template<int BN>
__device__ __forceinline__ void gemm_bodyT(
    const __nv_bfloat16* __restrict__ Ahi, const __nv_bfloat16* __restrict__ Alo,
    const __nv_bfloat16* __restrict__ Bhi, const __nv_bfloat16* __restrict__ Blo,
    float* __restrict__ C, float alpha, char* smem)
{
    constexpr int NT = GemmCfg<BN>::NT;
    const int tid  = threadIdx.x;
    const int wid  = tid >> 5;
    const int lane = tid & 31;
    const int m0 = blockIdx.y * 128;
    const int n0 = blockIdx.x * BN;
    const int wm0 = (wid & 3) * 32;
    const int wn0 = (wid >> 2) * (BN / 2);
    const uint32_t sb = smem_u32(smem);

    float acc[2][NT][4];
#pragma unroll
    for (int mt = 0; mt < 2; mt++)
#pragma unroll
        for (int nt = 0; nt < NT; nt++)
#pragma unroll
            for (int i = 0; i < 4; i++) acc[mt][nt][i] = 0.f;

    load_stageT<BN>(sb, 0, Ahi, Alo, Bhi, Blo, m0, n0, 0,  tid);
    load_stageT<BN>(sb, 1, Ahi, Alo, Bhi, Blo, m0, n0, 32, tid);

    const int lr = lane & 15;
    const int lc = lane >> 4;

    asm volatile("cp.async.wait_group 1;" ::: "memory");
    __syncthreads();

    FragSetT<NT> cur, nxt;
    int stage = 0;
    uint32_t st = sb;
    ld_fragsT<BN>(cur, st, lc, wm0, wn0, lr);

    for (int kt = 0; kt < 32; kt++) {
        ld_fragsT<BN>(nxt, st, 2 + lc, wm0, wn0, lr);
        mma_setT<BN>(acc, cur);
        if (kt < 31) {
            if (kt < 30) {
                int ns = stage + 2; if (ns >= 3) ns -= 3;
                load_stageT<BN>(sb, ns, Ahi, Alo, Bhi, Blo, m0, n0,
                                (kt + 2) * 32, tid);
                asm volatile("cp.async.wait_group 1;" ::: "memory");
            } else {
                asm volatile("cp.async.wait_group 0;" ::: "memory");
            }
            __syncthreads();
            stage++; if (stage == 3) stage = 0;
            st = sb + stage * GemmCfg<BN>::STG;
            ld_fragsT<BN>(cur, st, lc, wm0, wn0, lr);
        }
        mma_setT<BN>(acc, nxt);
    }

    const int er = lane >> 2;
    const int ec = (lane & 3) << 1;
#pragma unroll
    for (int mt = 0; mt < 2; mt++)
#pragma unroll
        for (int nt = 0; nt < NT; nt++) {
            int row = m0 + wm0 + mt * 16 + er;
            int col = n0 + wn0 + nt * 8 + ec;
            float2 v0 = make_float2(acc[mt][nt][0] * alpha, acc[mt][nt][1] * alpha);
            float2 v1 = make_float2(acc[mt][nt][2] * alpha, acc[mt][nt][3] * alpha);
            *(float2*)(C + (size_t)row * DIMN + col)       = v0;
            *(float2*)(C + (size_t)(row + 8) * DIMN + col) = v1;
        }
}

#define SMEM_GEMM4 (3 * GemmCfg<64>::STG)    // 73728
#define SMEM_GEMMO (3 * GemmCfg<32>::STG)    // 61440

__global__ __launch_bounds__(256, 2) void gemm4_kernel()
{
    extern __shared__ char smem[];
    const int z = blockIdx.z;
    const __nv_bfloat16* Bhi = g_Whi + (size_t)z * DIMN * DIMN;
    const __nv_bfloat16* Blo = g_Wlo + (size_t)z * DIMN * DIMN;
    float* outs[4] = {g_q, g_k, g_v, g_g};
    float alpha = (z == 0) ? QSCALE : 1.f;
    gemm_bodyT<64>(g_xhi, g_xlo, Bhi, Blo, outs[z], alpha, smem);
}

__global__ __launch_bounds__(256, 2) void gemmo_kernel(float* __restrict__ out)
{
    extern __shared__ char smem[];
    gemm_bodyT<32>(g_onhi, g_onlo, g_Whi + (size_t)4 * DIMN * DIMN,
                   g_Wlo + (size_t)4 * DIMN * DIMN, out, 1.f, smem);
}

// ---------------------------------------------------------------------------
// Fused low-rank gate path, 16 rows per block (64 blocks). (round-12 exact)
// ---------------------------------------------------------------------------
__global__ __launch_bounds__(256) void lowrank_gk_kernel(
    const float* __restrict__ x, const float* __restrict__ Wgk1,
    const float* __restrict__ Wgk2, const float* __restrict__ bgk2)
{
    const int m0  = blockIdx.x * 16;
    const int tid = threadIdx.x;

    __shared__ float sX[16][64];
    __shared__ float sPart[16][16][16];   // [kk][r][c]
    __shared__ float sT1[16][16];         // [r][c]

    const int kk = tid >> 4;   // 0..15
    const int cc = tid & 15;   // 0..15

    float acc16[16];
#pragma unroll
    for (int r = 0; r < 16; r++) acc16[r] = 0.f;

    for (int kc = 0; kc < 16; kc++) {
        {
            int row = tid >> 4, c4 = (tid & 15) << 2;
            *(float4*)&sX[row][c4] =
                *(const float4*)(x + (size_t)(m0 + row) * DIMN + kc * 64 + c4);
        }
        __syncthreads();
#pragma unroll
        for (int i = 0; i < 4; i++) {
            int k = kk * 4 + i;
            float w1 = Wgk1[(kc * 64 + k) * 16 + cc];
#pragma unroll
            for (int r = 0; r < 16; r++)
                acc16[r] = fmaf(sX[r][k], w1, acc16[r]);
        }
        __syncthreads();
    }
#pragma unroll
    for (int r = 0; r < 16; r++) sPart[kk][r][cc] = acc16[r];
    __syncthreads();

    {
        int rr = tid >> 4;
        float s = 0.f;
#pragma unroll
        for (int j = 0; j < 16; j++) s += sPart[j][rr][cc];
        sT1[rr][cc] = s;
    }
    __syncthreads();

#pragma unroll
    for (int u = 0; u < 4; u++) {
        int n = u * 256 + tid;
        float w2[16];
#pragma unroll
        for (int j = 0; j < 16; j++) w2[j] = Wgk2[j * DIMN + n];
        float bias = bgk2[n];
#pragma unroll
        for (int r = 0; r < 16; r++) {
            float a = bias;
#pragma unroll
            for (int j = 0; j < 16; j++)
                a = fmaf(sT1[r][j], w2[j], a);
            float ls = fminf(a, 0.f) - log1pf(__expf(-fabsf(a)));
            g_gk[(size_t)(m0 + r) * DIMN + n] = ls * GNORM;
        }
    }
}

// ---------------------------------------------------------------------------
// Chunked GLA
// ---------------------------------------------------------------------------
__device__ __forceinline__ int row_off(int b, int h, int t)
{
    return (((b * TT + t) * HH + h) << 7);
}

// Fused prep + chunk_kv, v-split into 2 halves (round-12 exact).
__global__ __launch_bounds__(512) void prep_kv_kernel()
{
    const int bid = blockIdx.x;
    const int bhc = bid >> 1, vh = bid & 1;
    const int bh  = bhc >> 3, c0 = bhc & 7;
    const int b   = bh >> 3,  h  = bh & 7;
    const int tid = threadIdx.x;
    const int ch  = tid & 127;
    const int tg  = tid >> 7;
    const int tb  = c0 * CH + tg * 16;

    __shared__ float gsum[4][128];
    __shared__ float sK[64][128];
    __shared__ float sV[16][64];

    float loc[16];
    {
        float a = 0.f;
#pragma unroll
        for (int s = 0; s < 16; s++) {
            loc[s] = g_gk[row_off(b, h, tb + s) + ch];
            a += loc[s];
        }
        gsum[tg][ch] = a;
    }
    __syncthreads();
    {
        float off = 0.f;
#pragma unroll
        for (int g = 0; g < 4; g++)
            if (g < tg) off += gsum[g][ch];
        float tot = gsum[0][ch] + gsum[1][ch] + gsum[2][ch] + gsum[3][ch];
        float bacc = off;
#pragma unroll 4
        for (int s = 0; s < 16; s++) {
            bacc += loc[s];
            int r = row_off(b, h, tb + s) + ch;
            float q = g_q[r], k = g_k[r];
            if (vh == 0) {
                g_qg[r] = q * __expf(bacc);
                g_kd[r] = k * __expf(-bacc);
            }
            sK[tg * 16 + s][ch] = k * __expf(tot - bacc);
        }
        if (vh == 0 && tg == 0) g_dc[bhc * 128 + ch] = __expf(tot);
    }
    __syncthreads();

    const int tr  = tid >> 4, tc = tid & 15;
    const int kr0 = tr << 2, vc0 = tc << 2;
    const int tbase = c0 * CH;
    const int vbase = vh * 64;

    float acc[4][4];
#pragma unroll
    for (int i = 0; i < 4; i++)
#pragma unroll
        for (int j = 0; j < 4; j++) acc[i][j] = 0.f;

    for (int st = 0; st < 4; st++) {
        if (tid < 256) {
            int sr = tid >> 4;
            int sc = (tid & 15) << 2;
            int r  = row_off(b, h, tbase + st * 16 + sr) + vbase + sc;
            *(float4*)&sV[sr][sc] = *(const float4*)(g_v + r);
        }
        __syncthreads();
#pragma unroll
        for (int ss = 0; ss < 16; ss++) {
            int s = st * 16 + ss;
            float4 k4 = *(const float4*)&sK[s][kr0];
            float4 v4 = *(const float4*)&sV[ss][vc0];
            float kr[4] = {k4.x,k4.y,k4.z,k4.w};
            float vr[4] = {v4.x,v4.y,v4.z,v4.w};
#pragma unroll
            for (int i = 0; i < 4; i++)
#pragma unroll
                for (int j = 0; j < 4; j++)
                    acc[i][j] = fmaf(kr[i], vr[j], acc[i][j]);
        }
        __syncthreads();
    }

    float* dst = g_kv + (size_t)bhc * 16384 + vbase;
#pragma unroll
    for (int i = 0; i < 4; i++)
        *(float4*)(dst + (kr0 + i) * 128 + vc0) =
            make_float4(acc[i][0], acc[i][1], acc[i][2], acc[i][3]);
}

// state scan v2 (round-12 exact)
__global__ __launch_bounds__(256) void state_scan_kernel()
{
    const int bh = blockIdx.x >> 4;
    const int vg = blockIdx.x & 15;
    const int tid = threadIdx.x;
    const int k  = tid >> 1;
    const int v0 = vg * 8 + (tid & 1) * 4;

    const size_t slab = (size_t)bh * NC * 16384 + (size_t)k * 128 + v0;
    const int dbase = bh * NC * 128 + k;

    float4 S = make_float4(0.f, 0.f, 0.f, 0.f);
    float4 kv = *(const float4*)(g_kv + slab);
    float  d  = g_dc[dbase];

    for (int c = 0; c < NC; c++) {
        *(float4*)(g_S + slab + (size_t)c * 16384) = S;
        S.x = fmaf(S.x, d, kv.x); S.y = fmaf(S.y, d, kv.y);
        S.z = fmaf(S.z, d, kv.z); S.w = fmaf(S.w, d, kv.w);
        if (c < NC - 1) {
            kv = *(const float4*)(g_kv + slab + (size_t)(c + 1) * 16384);
            d  = g_dc[dbase + (c + 1) * 128];
        }
    }
}

// chunk_out (round-12 exact): 128 blocks, fused gated RMSNorm, bf16 output.
__global__ __launch_bounds__(256) void chunk_out_kernel(
    const float* __restrict__ g_norm_w)
{
    const int bhc = blockIdx.x;
    const int bh  = bhc >> 3, c0 = bhc & 7;
    const int b   = bh >> 3,  h  = bh & 7;
    const int tid = threadIdx.x;
    const int tr  = tid >> 4, tc = tid & 15;
    const int t0  = tr << 2;
    const int v0  = tc << 3;
    const int tbase = c0 * CH;

    __shared__ float sQ [16][68];
    __shared__ float sKd[16][68];
    __shared__ float sS [16][128];
    __shared__ float sA [64][68];
    __shared__ float sV [16][128];

    float o[4][8];
    float a2[4][4];
#pragma unroll
    for (int i = 0; i < 4; i++) {
#pragma unroll
        for (int j = 0; j < 8; j++) o[i][j] = 0.f;
#pragma unroll
        for (int j = 0; j < 4; j++) a2[i][j] = 0.f;
    }

    const size_t Sbase = (size_t)bhc * 16384;

    for (int k0 = 0; k0 < 128; k0 += 16) {
        {
            int tt = tid >> 2;
            int c4 = (tid & 3) << 2;
            int r  = row_off(b, h, tbase + tt) + k0 + c4;
            float4 qv = *(const float4*)(g_qg + r);
            sQ[c4+0][tt] = qv.x; sQ[c4+1][tt] = qv.y;
            sQ[c4+2][tt] = qv.z; sQ[c4+3][tt] = qv.w;
            float4 kv = *(const float4*)(g_kd + r);
            sKd[c4+0][tt] = kv.x; sKd[c4+1][tt] = kv.y;
            sKd[c4+2][tt] = kv.z; sKd[c4+3][tt] = kv.w;
        }
#pragma unroll
        for (int u = 0; u < 2; u++) {
            int f  = tid + (u << 8);
            int sr = f >> 5;
            int sc = (f & 31) << 2;
            *(float4*)&sS[sr][sc] =
                *(const float4*)(g_S + Sbase + (k0 + sr) * 128 + sc);
        }
        __syncthreads();

#pragma unroll
        for (int kk = 0; kk < 16; kk++) {
            float4 q4  = *(const float4*)&sQ[kk][t0];
            float4 s0  = *(const float4*)&sS[kk][v0];
            float4 s1  = *(const float4*)&sS[kk][v0 + 4];
            float4 kd4 = *(const float4*)&sKd[kk][tc << 2];
            float qr[4] = {q4.x, q4.y, q4.z, q4.w};
            float sr_[8] = {s0.x,s0.y,s0.z,s0.w,s1.x,s1.y,s1.z,s1.w};
            float kr[4] = {kd4.x,kd4.y,kd4.z,kd4.w};
#pragma unroll
            for (int i = 0; i < 4; i++) {
#pragma unroll
                for (int j = 0; j < 8; j++)
                    o[i][j] = fmaf(qr[i], sr_[j], o[i][j]);
#pragma unroll
                for (int j = 0; j < 4; j++)
                    a2[i][j] = fmaf(qr[i], kr[j], a2[i][j]);
            }
        }
        __syncthreads();
    }

#pragma unroll
    for (int i = 0; i < 4; i++) {
        int t = t0 + i;
#pragma unroll
        for (int j = 0; j < 4; j++) {
            int s = (tc << 2) + j;
            sA[t][s] = (s <= t) ? a2[i][j] : 0.f;
        }
    }
    __syncthreads();

    for (int st = 0; st < 4; st++) {
#pragma unroll
        for (int u = 0; u < 2; u++) {
            int f  = tid + (u << 8);
            int sr = f >> 5;
            int sc = (f & 31) << 2;
            int r  = row_off(b, h, tbase + st * 16 + sr) + sc;
            *(float4*)&sV[sr][sc] = *(const float4*)(g_v + r);
        }
        __syncthreads();
#pragma unroll
        for (int ss = 0; ss < 16; ss++) {
            int s = st * 16 + ss;
            float a[4];
#pragma unroll
            for (int i = 0; i < 4; i++) a[i] = sA[t0 + i][s];
            float4 vv0 = *(const float4*)&sV[ss][v0];
            float4 vv1 = *(const float4*)&sV[ss][v0 + 4];
            float vr[8] = {vv0.x,vv0.y,vv0.z,vv0.w,vv1.x,vv1.y,vv1.z,vv1.w};
#pragma unroll
            for (int i = 0; i < 4; i++)
#pragma unroll
                for (int j = 0; j < 8; j++)
                    o[i][j] = fmaf(a[i], vr[j], o[i][j]);
        }
        __syncthreads();
    }

    float4 w0 = *(const float4*)(g_norm_w + v0);
    float4 w1 = *(const float4*)(g_norm_w + v0 + 4);
    float wr[8] = {w0.x,w0.y,w0.z,w0.w,w1.x,w1.y,w1.z,w1.w};

#pragma unroll
    for (int i = 0; i < 4; i++) {
        float ss = 0.f;
#pragma unroll
        for (int j = 0; j < 8; j++) ss = fmaf(o[i][j], o[i][j], ss);
#pragma unroll
        for (int off = 1; off < 16; off <<= 1)
            ss += __shfl_xor_sync(0xffffffffu, ss, off);
        float rms = rsqrtf(ss * (1.f / 128.f) + 1e-5f);

        int r = row_off(b, h, tbase + t0 + i);
        float4 gg0 = *(const float4*)(g_g + r + v0);
        float4 gg1 = *(const float4*)(g_g + r + v0 + 4);
        float gr[8] = {gg0.x,gg0.y,gg0.z,gg0.w,gg1.x,gg1.y,gg1.z,gg1.w};

        union { __nv_bfloat16 h[8]; uint4 u; } hh;
        union { __nv_bfloat16 h[8]; uint4 u; } ll;
#pragma unroll
        for (int j = 0; j < 8; j++) {
            float gvv = gr[j];
            float sw  = gvv / (1.f + __expf(-gvv));
            float on  = o[i][j] * rms * wr[j] * sw;
            split_bf16(on, hh.h[j], ll.h[j]);
        }
        *(uint4*)&g_onhi[r + v0] = hh.u;
        *(uint4*)&g_onlo[r + v0] = ll.u;
    }
}

// ---------------------------------------------------------------------------
extern "C" void kernel_launch(void* const* d_in, const int* in_sizes, int n_in,
                              void* d_out, int out_size)
{
    const float* x        = (const float*)d_in[0];
    const float* Wq       = (const float*)d_in[1];
    const float* Wk       = (const float*)d_in[2];
    const float* Wv       = (const float*)d_in[3];
    const float* Wg       = (const float*)d_in[4];
    const float* Wgk1     = (const float*)d_in[5];
    const float* Wgk2     = (const float*)d_in[6];
    const float* bgk2     = (const float*)d_in[7];
    const float* g_norm_w = (const float*)d_in[8];
    const float* Wo       = (const float*)d_in[9];
    float* out = (float*)d_out;

    // Host-side attribute set; executed during capture, not a graph node.
    cudaFuncSetAttribute(gemm4_kernel,
        cudaFuncAttributeMaxDynamicSharedMemorySize, SMEM_GEMM4);
    cudaFuncSetAttribute(gemmo_kernel,
        cudaFuncAttributeMaxDynamicSharedMemorySize, SMEM_GEMMO);

    conv_w_kernel<<<dim3(32, 32, 5), dim3(256)>>>(Wq, Wk, Wv, Wg, Wo);
    conv_x_kernel<<<1024, 256>>>(x);
    lowrank_gk_kernel<<<64, 256>>>(x, Wgk1, Wgk2, bgk2);
    gemm4_kernel<<<dim3(16, 8, 4), 256, SMEM_GEMM4>>>();
    prep_kv_kernel<<<256, 512>>>();
    state_scan_kernel<<<256, 256>>>();
    chunk_out_kernel<<<128, 256>>>(g_norm_w);
    gemmo_kernel<<<dim3(32, 8), 256, SMEM_GEMMO>>>(out);
}

// round 16
// speedup vs baseline: 1.2927x; 1.0345x over previous
#include <cuda_runtime.h>
#include <cuda_bf16.h>
#include <math.h>
#include <cstdint>

// Shapes (fixed)
#define DIMN   1024
#define BB     2
#define TT     512
#define HH     8
#define HKD    128
#define NROWS  (BB*TT)          // 1024
#define CH     64               // chunk length
#define NC     (TT/CH)          // 8 chunks
#define QSCALE 0.08838834764831845f   // 128^-0.5
#define GNORM  0.0625f                // 1/16

// ---------------------------------------------------------------------------
// Scratch (no cudaMalloc allowed)
// ---------------------------------------------------------------------------
__device__ float g_q [NROWS*DIMN];
__device__ float g_k [NROWS*DIMN];
__device__ float g_v [NROWS*DIMN];
__device__ float g_g [NROWS*DIMN];
__device__ float g_gk[NROWS*DIMN];
// chunked-GLA scratch
__device__ float g_qg[NROWS*DIMN];
__device__ float g_kd[NROWS*DIMN];
__device__ float g_kv[16*NC*HKD*HKD];
__device__ float g_S [16*NC*HKD*HKD];
__device__ float g_dc[16*NC*HKD];
// bf16 split-precision operands
__device__ __nv_bfloat16 g_xhi [NROWS*DIMN];
__device__ __nv_bfloat16 g_xlo [NROWS*DIMN];
__device__ __nv_bfloat16 g_onhi[NROWS*DIMN];
__device__ __nv_bfloat16 g_onlo[NROWS*DIMN];
__device__ __nv_bfloat16 g_Whi [5*DIMN*DIMN];   // transposed: [n][k]
__device__ __nv_bfloat16 g_Wlo [5*DIMN*DIMN];

// ---------------------------------------------------------------------------
// PTX helpers (all non-'a'-gated: cp.async / ldmatrix / mma.sync)
// ---------------------------------------------------------------------------
__device__ __forceinline__ uint32_t smem_u32(const void* p) {
    uint32_t a;
    asm("{ .reg .u64 t; cvta.to.shared.u64 t, %1; cvt.u32.u64 %0, t; }"
        : "=r"(a) : "l"(p));
    return a;
}
__device__ __forceinline__ void cp16(uint32_t dst, const void* src) {
    asm volatile("cp.async.cg.shared.global [%0], [%1], 16;"
                 :: "r"(dst), "l"(src) : "memory");
}
__device__ __forceinline__ void cp_commit() {
    asm volatile("cp.async.commit_group;" ::: "memory");
}
__device__ __forceinline__ void ldsm4(uint32_t& r0, uint32_t& r1,
                                      uint32_t& r2, uint32_t& r3, uint32_t a) {
    asm volatile("ldmatrix.sync.aligned.m8n8.x4.shared.b16 {%0,%1,%2,%3}, [%4];"
                 : "=r"(r0), "=r"(r1), "=r"(r2), "=r"(r3) : "r"(a));
}
__device__ __forceinline__ void mma16816(float* c, const uint32_t* a,
                                         const uint32_t* b) {
    asm volatile("mma.sync.aligned.m16n8k16.row.col.f32.bf16.bf16.f32 "
        "{%0,%1,%2,%3}, {%4,%5,%6,%7}, {%8,%9}, {%0,%1,%2,%3};"
        : "+f"(c[0]), "+f"(c[1]), "+f"(c[2]), "+f"(c[3])
        : "r"(a[0]), "r"(a[1]), "r"(a[2]), "r"(a[3]), "r"(b[0]), "r"(b[1]));
}

__device__ __forceinline__ void split_bf16(float x, __nv_bfloat16& h, __nv_bfloat16& l) {
    h = __float2bfloat16(x);
    l = __float2bfloat16(x - __bfloat162float(h));
}

// NOTE: device globals are referenced INSIDE kernels only (host-side symbol
// would be the ATS shadow -> silent wrong-memory writes).
__global__ __launch_bounds__(256) void conv_x_kernel(const float* __restrict__ x)
{
    int i = blockIdx.x * 256 + threadIdx.x;       // float4 index
    float4 v = ((const float4*)x)[i];
    __nv_bfloat16 h[4], l[4];
    split_bf16(v.x, h[0], l[0]); split_bf16(v.y, h[1], l[1]);
    split_bf16(v.z, h[2], l[2]); split_bf16(v.w, h[3], l[3]);
    __nv_bfloat162* ph = (__nv_bfloat162*)g_xhi;
    __nv_bfloat162* pl = (__nv_bfloat162*)g_xlo;
    ph[i*2]   = __nv_bfloat162(h[0], h[1]);
    ph[i*2+1] = __nv_bfloat162(h[2], h[3]);
    pl[i*2]   = __nv_bfloat162(l[0], l[1]);
    pl[i*2+1] = __nv_bfloat162(l[2], l[3]);
}

// W fp32 [k][n] -> transposed bf16 hi/lo [n][k] (5 weights via z)
__global__ __launch_bounds__(256) void conv_w_kernel(
    const float* __restrict__ Wq, const float* __restrict__ Wk,
    const float* __restrict__ Wv, const float* __restrict__ Wg,
    const float* __restrict__ Wo)
{
    const float* Ws[5] = {Wq, Wk, Wv, Wg, Wo};
    const float* W = Ws[blockIdx.z];
    __nv_bfloat16* Dhi = g_Whi + (size_t)blockIdx.z * DIMN * DIMN;
    __nv_bfloat16* Dlo = g_Wlo + (size_t)blockIdx.z * DIMN * DIMN;

    __shared__ float s[32][33];
    int tx = threadIdx.x & 31, ty = threadIdx.x >> 5;   // 32 x 8
    int kt = blockIdx.y * 32, nt = blockIdx.x * 32;
#pragma unroll
    for (int j = 0; j < 4; j++)
        s[ty + j*8][tx] = W[(kt + ty + j*8) * DIMN + nt + tx];
    __syncthreads();
#pragma unroll
    for (int j = 0; j < 4; j++) {
        int n = nt + ty + j*8, k = kt + tx;
        float w = s[tx][ty + j*8];
        __nv_bfloat16 h, l; split_bf16(w, h, l);
        Dhi[(size_t)n * DIMN + k] = h;
        Dlo[(size_t)n * DIMN + k] = l;
    }
}

// ---------------------------------------------------------------------------
// HMMA split-3 GEMM, templated on BN (64 for gemm4, 32 for gemmo).
// Block tile 128xBN, BK=32, 8 warps (4m x 2n), 3-stage cp.async +
// register fragment double-buffering, 1 sync per K-step.
// ---------------------------------------------------------------------------
#define O_AHI 0
#define O_ALO 8192
#define O_BHI 16384

template<int BN> struct GemmCfg {
    static constexpr int STG   = 16384 + BN * 128;   // stage bytes
    static constexpr int NT    = BN / 16;            // n-subtiles per warp
    static constexpr int O_BLO = 16384 + BN * 64;
};

__device__ __forceinline__ uint32_t sw_addr(uint32_t region, int row, int chunk) {
    return region + row * 64 + ((chunk ^ ((row >> 1) & 3)) << 4);
}

template<int BN>
__device__ __forceinline__ void load_stageT(
    uint32_t sb, int s,
    const __nv_bfloat16* __restrict__ Ahi, const __nv_bfloat16* __restrict__ Alo,
    const __nv_bfloat16* __restrict__ Bhi, const __nv_bfloat16* __restrict__ Blo,
    int m0, int n0, int k0, int tid)
{
    uint32_t st = sb + s * GemmCfg<BN>::STG;
#pragma unroll
    for (int i = 0; i < 2; i++) {
        int idx = tid + (i << 8);          // 0..511
        int row = idx >> 2, c = idx & 3;
        const size_t go = (size_t)(m0 + row) * DIMN + k0 + c * 8;
        cp16(sw_addr(st + O_AHI, row, c), Ahi + go);
        cp16(sw_addr(st + O_ALO, row, c), Alo + go);
    }
    if (BN == 64) {
        int row = tid >> 2, c = tid & 3;   // 64 rows x 4 chunks
        const size_t go = (size_t)(n0 + row) * DIMN + k0 + c * 8;
        cp16(sw_addr(st + O_BHI, row, c), Bhi + go);
        cp16(sw_addr(st + GemmCfg<BN>::O_BLO, row, c), Blo + go);
    } else {
        if (tid < BN * 4) {
            int row = tid >> 2, c = tid & 3;
            const size_t go = (size_t)(n0 + row) * DIMN + k0 + c * 8;
            cp16(sw_addr(st + O_BHI, row, c), Bhi + go);
            cp16(sw_addr(st + GemmCfg<BN>::O_BLO, row, c), Blo + go);
        }
    }
    cp_commit();
}

template<int NT> struct FragSetT {
    uint32_t ahi[2][4], alo[2][4];
    uint32_t bhi[NT][2], blo[NT][2];
};

template<int BN>
__device__ __forceinline__ void ld_fragsT(FragSetT<GemmCfg<BN>::NT>& f,
                                          uint32_t st, int ch,
                                          int wm0, int wn0, int lr)
{
#pragma unroll
    for (int mt = 0; mt < 2; mt++) {
        int row = wm0 + mt * 16 + lr;
        ldsm4(f.ahi[mt][0], f.ahi[mt][1], f.ahi[mt][2], f.ahi[mt][3],
              sw_addr(st + O_AHI, row, ch));
        ldsm4(f.alo[mt][0], f.alo[mt][1], f.alo[mt][2], f.alo[mt][3],
              sw_addr(st + O_ALO, row, ch));
    }
#pragma unroll
    for (int ng = 0; ng < GemmCfg<BN>::NT / 2; ng++) {
        int row = wn0 + ng * 16 + lr;
        uint32_t t0, t1, t2, t3;
        ldsm4(t0, t1, t2, t3, sw_addr(st + O_BHI, row, ch));
        f.bhi[ng*2][0] = t0; f.bhi[ng*2+1][0] = t1;
        f.bhi[ng*2][1] = t2; f.bhi[ng*2+1][1] = t3;
        ldsm4(t0, t1, t2, t3, sw_addr(st + GemmCfg<BN>::O_BLO, row, ch));
        f.blo[ng*2][0] = t0; f.blo[ng*2+1][0] = t1;
        f.blo[ng*2][1] = t2; f.blo[ng*2+1][1] = t3;
    }
}

template<int BN>
__device__ __forceinline__ void mma_setT(float acc[2][GemmCfg<BN>::NT][4],
                                         const FragSetT<GemmCfg<BN>::NT>& f)
{
#pragma unroll
    for (int mt = 0; mt < 2; mt++)
#pragma unroll
        for (int nt = 0; nt < GemmCfg<BN>::NT; nt++) {
            mma16816(acc[mt][nt], f.ahi[mt], f.bhi[nt]);
            mma16816(acc[mt][nt], f.ahi[mt], f.blo[nt]);
            mma16816(acc[mt][nt], f.alo[mt], f.bhi[nt]);
        }
}

template<int BN>
__device__ __forceinline__ void gemm_bodyT(
    const __nv_bfloat16* __restrict__ Ahi, const __nv_bfloat16* __restrict__ Alo,
    const __nv_bfloat16* __restrict__ Bhi, const __nv_bfloat16* __restrict__ Blo,
    float* __restrict__ C, float alpha, char* smem)
{
    constexpr int NT = GemmCfg<BN>::NT;
    const int tid  = threadIdx.x;
    const int wid  = tid >> 5;
    const int lane = tid & 31;
    const int m0 = blockIdx.y * 128;
    const int n0 = blockIdx.x * BN;
    const int wm0 = (wid & 3) * 32;
    const int wn0 = (wid >> 2) * (BN / 2);
    const uint32_t sb = smem_u32(smem);

    float acc[2][NT][4];
#pragma unroll
    for (int mt = 0; mt < 2; mt++)
#pragma unroll
        for (int nt = 0; nt < NT; nt++)
#pragma unroll
            for (int i = 0; i < 4; i++) acc[mt][nt][i] = 0.f;

    load_stageT<BN>(sb, 0, Ahi, Alo, Bhi, Blo, m0, n0, 0,  tid);
    load_stageT<BN>(sb, 1, Ahi, Alo, Bhi, Blo, m0, n0, 32, tid);

    const int lr = lane & 15;
    const int lc = lane >> 4;

    asm volatile("cp.async.wait_group 1;" ::: "memory");
    __syncthreads();

    FragSetT<NT> cur, nxt;
    int stage = 0;
    uint32_t st = sb;
    ld_fragsT<BN>(cur, st, lc, wm0, wn0, lr);

    for (int kt = 0; kt < 32; kt++) {
        ld_fragsT<BN>(nxt, st, 2 + lc, wm0, wn0, lr);
        mma_setT<BN>(acc, cur);
        if (kt < 31) {
            if (kt < 30) {
                int ns = stage + 2; if (ns >= 3) ns -= 3;
                load_stageT<BN>(sb, ns, Ahi, Alo, Bhi, Blo, m0, n0,
                                (kt + 2) * 32, tid);
                asm volatile("cp.async.wait_group 1;" ::: "memory");
            } else {
                asm volatile("cp.async.wait_group 0;" ::: "memory");
            }
            __syncthreads();
            stage++; if (stage == 3) stage = 0;
            st = sb + stage * GemmCfg<BN>::STG;
            ld_fragsT<BN>(cur, st, lc, wm0, wn0, lr);
        }
        mma_setT<BN>(acc, nxt);
    }

    const int er = lane >> 2;
    const int ec = (lane & 3) << 1;
#pragma unroll
    for (int mt = 0; mt < 2; mt++)
#pragma unroll
        for (int nt = 0; nt < NT; nt++) {
            int row = m0 + wm0 + mt * 16 + er;
            int col = n0 + wn0 + nt * 8 + ec;
            float2 v0 = make_float2(acc[mt][nt][0] * alpha, acc[mt][nt][1] * alpha);
            float2 v1 = make_float2(acc[mt][nt][2] * alpha, acc[mt][nt][3] * alpha);
            *(float2*)(C + (size_t)row * DIMN + col)       = v0;
            *(float2*)(C + (size_t)(row + 8) * DIMN + col) = v1;
        }
}

#define SMEM_GEMM4 (3 * GemmCfg<64>::STG)    // 73728
#define SMEM_GEMMO (3 * GemmCfg<32>::STG)    // 61440

__global__ __launch_bounds__(256, 2) void gemm4_kernel()
{
    extern __shared__ char smem[];
    const int z = blockIdx.z;
    const __nv_bfloat16* Bhi = g_Whi + (size_t)z * DIMN * DIMN;
    const __nv_bfloat16* Blo = g_Wlo + (size_t)z * DIMN * DIMN;
    float* outs[4] = {g_q, g_k, g_v, g_g};
    float alpha = (z == 0) ? QSCALE : 1.f;
    gemm_bodyT<64>(g_xhi, g_xlo, Bhi, Blo, outs[z], alpha, smem);
}

__global__ __launch_bounds__(256, 2) void gemmo_kernel(float* __restrict__ out)
{
    extern __shared__ char smem[];
    gemm_bodyT<32>(g_onhi, g_onlo, g_Whi + (size_t)4 * DIMN * DIMN,
                   g_Wlo + (size_t)4 * DIMN * DIMN, out, 1.f, smem);
}

// ---------------------------------------------------------------------------
// Fused low-rank gate path, 16 rows per block (64 blocks).
// ---------------------------------------------------------------------------
__global__ __launch_bounds__(256) void lowrank_gk_kernel(
    const float* __restrict__ x, const float* __restrict__ Wgk1,
    const float* __restrict__ Wgk2, const float* __restrict__ bgk2)
{
    const int m0  = blockIdx.x * 16;
    const int tid = threadIdx.x;

    __shared__ float sX[16][64];
    __shared__ float sPart[16][16][16];   // [kk][r][c]
    __shared__ float sT1[16][16];         // [r][c]

    const int kk = tid >> 4;   // 0..15
    const int cc = tid & 15;   // 0..15

    float acc16[16];
#pragma unroll
    for (int r = 0; r < 16; r++) acc16[r] = 0.f;

    for (int kc = 0; kc < 16; kc++) {
        {
            int row = tid >> 4, c4 = (tid & 15) << 2;
            *(float4*)&sX[row][c4] =
                *(const float4*)(x + (size_t)(m0 + row) * DIMN + kc * 64 + c4);
        }
        __syncthreads();
#pragma unroll
        for (int i = 0; i < 4; i++) {
            int k = kk * 4 + i;
            float w1 = Wgk1[(kc * 64 + k) * 16 + cc];
#pragma unroll
            for (int r = 0; r < 16; r++)
                acc16[r] = fmaf(sX[r][k], w1, acc16[r]);
        }
        __syncthreads();
    }
#pragma unroll
    for (int r = 0; r < 16; r++) sPart[kk][r][cc] = acc16[r];
    __syncthreads();

    {
        int rr = tid >> 4;
        float s = 0.f;
#pragma unroll
        for (int j = 0; j < 16; j++) s += sPart[j][rr][cc];
        sT1[rr][cc] = s;
    }
    __syncthreads();

#pragma unroll
    for (int u = 0; u < 4; u++) {
        int n = u * 256 + tid;
        float w2[16];
#pragma unroll
        for (int j = 0; j < 16; j++) w2[j] = Wgk2[j * DIMN + n];
        float bias = bgk2[n];
#pragma unroll
        for (int r = 0; r < 16; r++) {
            float a = bias;
#pragma unroll
            for (int j = 0; j < 16; j++)
                a = fmaf(sT1[r][j], w2[j], a);
            float ls = fminf(a, 0.f) - log1pf(__expf(-fabsf(a)));
            g_gk[(size_t)(m0 + r) * DIMN + n] = ls * GNORM;
        }
    }
}

// ---------------------------------------------------------------------------
// Chunked GLA
// ---------------------------------------------------------------------------
__device__ __forceinline__ int row_off(int b, int h, int t)
{
    return (((b * TT + t) * HH + h) << 7);
}

// Fused prep + chunk_kv, v-split into 2 halves (round-12 proven).
__global__ __launch_bounds__(512) void prep_kv_kernel()
{
    const int bid = blockIdx.x;
    const int bhc = bid >> 1, vh = bid & 1;
    const int bh  = bhc >> 3, c0 = bhc & 7;
    const int b   = bh >> 3,  h  = bh & 7;
    const int tid = threadIdx.x;
    const int ch  = tid & 127;
    const int tg  = tid >> 7;
    const int tb  = c0 * CH + tg * 16;

    __shared__ float gsum[4][128];
    __shared__ float sK[64][128];
    __shared__ float sV[16][64];

    float loc[16];
    {
        float a = 0.f;
#pragma unroll
        for (int s = 0; s < 16; s++) {
            loc[s] = g_gk[row_off(b, h, tb + s) + ch];
            a += loc[s];
        }
        gsum[tg][ch] = a;
    }
    __syncthreads();
    {
        float off = 0.f;
#pragma unroll
        for (int g = 0; g < 4; g++)
            if (g < tg) off += gsum[g][ch];
        float tot = gsum[0][ch] + gsum[1][ch] + gsum[2][ch] + gsum[3][ch];
        float bacc = off;
#pragma unroll 4
        for (int s = 0; s < 16; s++) {
            bacc += loc[s];
            int r = row_off(b, h, tb + s) + ch;
            float q = g_q[r], k = g_k[r];
            if (vh == 0) {
                g_qg[r] = q * __expf(bacc);
                g_kd[r] = k * __expf(-bacc);
            }
            sK[tg * 16 + s][ch] = k * __expf(tot - bacc);
        }
        if (vh == 0 && tg == 0) g_dc[bhc * 128 + ch] = __expf(tot);
    }
    __syncthreads();

    const int tr  = tid >> 4, tc = tid & 15;
    const int kr0 = tr << 2, vc0 = tc << 2;
    const int tbase = c0 * CH;
    const int vbase = vh * 64;

    float acc[4][4];
#pragma unroll
    for (int i = 0; i < 4; i++)
#pragma unroll
        for (int j = 0; j < 4; j++) acc[i][j] = 0.f;

    for (int st = 0; st < 4; st++) {
        if (tid < 256) {
            int sr = tid >> 4;
            int sc = (tid & 15) << 2;
            int r  = row_off(b, h, tbase + st * 16 + sr) + vbase + sc;
            *(float4*)&sV[sr][sc] = *(const float4*)(g_v + r);
        }
        __syncthreads();
#pragma unroll
        for (int ss = 0; ss < 16; ss++) {
            int s = st * 16 + ss;
            float4 k4 = *(const float4*)&sK[s][kr0];
            float4 v4 = *(const float4*)&sV[ss][vc0];
            float kr[4] = {k4.x,k4.y,k4.z,k4.w};
            float vr[4] = {v4.x,v4.y,v4.z,v4.w};
#pragma unroll
            for (int i = 0; i < 4; i++)
#pragma unroll
                for (int j = 0; j < 4; j++)
                    acc[i][j] = fmaf(kr[i], vr[j], acc[i][j]);
        }
        __syncthreads();
    }

    float* dst = g_kv + (size_t)bhc * 16384 + vbase;
#pragma unroll
    for (int i = 0; i < 4; i++)
        *(float4*)(dst + (kr0 + i) * 128 + vc0) =
            make_float4(acc[i][0], acc[i][1], acc[i][2], acc[i][3]);
}

// state scan v2 (round-12 proven)
__global__ __launch_bounds__(256) void state_scan_kernel()
{
    const int bh = blockIdx.x >> 4;
    const int vg = blockIdx.x & 15;
    const int tid = threadIdx.x;
    const int k  = tid >> 1;
    const int v0 = vg * 8 + (tid & 1) * 4;

    const size_t slab = (size_t)bh * NC * 16384 + (size_t)k * 128 + v0;
    const int dbase = bh * NC * 128 + k;

    float4 S = make_float4(0.f, 0.f, 0.f, 0.f);
    float4 kv = *(const float4*)(g_kv + slab);
    float  d  = g_dc[dbase];

    for (int c = 0; c < NC; c++) {
        *(float4*)(g_S + slab + (size_t)c * 16384) = S;
        S.x = fmaf(S.x, d, kv.x); S.y = fmaf(S.y, d, kv.y);
        S.z = fmaf(S.z, d, kv.z); S.w = fmaf(S.w, d, kv.w);
        if (c < NC - 1) {
            kv = *(const float4*)(g_kv + slab + (size_t)(c + 1) * 16384);
            d  = g_dc[dbase + (c + 1) * 128];
        }
    }
}

// chunk_out t-split: 256 blocks (bhc x t-half of 32 rows).
// 8 warps x 4 t-rows; lane owns 4 v-cols; full-warp shuffle RMS.
__global__ __launch_bounds__(256) void chunk_out_kernel(
    const float* __restrict__ g_norm_w)
{
    const int bid = blockIdx.x;
    const int bhc = bid >> 1, th = bid & 1;
    const int bh  = bhc >> 3, c0 = bhc & 7;
    const int b   = bh >> 3,  h  = bh & 7;
    const int tid = threadIdx.x;
    const int wr  = tid >> 5;          // 0..7
    const int lane = tid & 31;
    const int t0  = wr << 2;           // local t base within half (0..28)
    const int v0  = lane << 2;         // 0..124
    const int tchunk = c0 * CH;
    const int tbase  = tchunk + th * 32;

    __shared__ float sQ [16][34];      // [k][t_local 32]
    __shared__ float sKd[16][68];      // [k][s 64]
    __shared__ float sS [16][128];
    __shared__ float sA [32][68];
    __shared__ float sV [16][128];

    float o[4][4];
    float a2[4][2];
#pragma unroll
    for (int i = 0; i < 4; i++) {
#pragma unroll
        for (int j = 0; j < 4; j++) o[i][j] = 0.f;
        a2[i][0] = 0.f; a2[i][1] = 0.f;
    }

    const size_t Sbase = (size_t)bhc * 16384;

    for (int k0 = 0; k0 < 128; k0 += 16) {
        {   // stage q~ for this half's 32 t-rows (transposed)
            int tl = tid >> 3;
            int k2 = (tid & 7) << 1;
            int r  = row_off(b, h, tbase + tl) + k0 + k2;
            float2 qv = *(const float2*)(g_qg + r);
            sQ[k2][tl] = qv.x; sQ[k2+1][tl] = qv.y;
        }
        {   // stage k^ for the FULL chunk's 64 s-rows (transposed)
            int sl = tid >> 2;
            int c4 = (tid & 3) << 2;
            int r  = row_off(b, h, tchunk + sl) + k0 + c4;
            float4 kv = *(const float4*)(g_kd + r);
            sKd[c4][sl] = kv.x; sKd[c4+1][sl] = kv.y;
            sKd[c4+2][sl] = kv.z; sKd[c4+3][sl] = kv.w;
        }
#pragma unroll
        for (int u = 0; u < 2; u++) {
            int f  = tid + (u << 8);
            int sr = f >> 5;
            int sc = (f & 31) << 2;
            *(float4*)&sS[sr][sc] =
                *(const float4*)(g_S + Sbase + (k0 + sr) * 128 + sc);
        }
        __syncthreads();

#pragma unroll
        for (int kk = 0; kk < 16; kk++) {
            float qr[4];
#pragma unroll
            for (int i = 0; i < 4; i++) qr[i] = sQ[kk][t0 + i];
            float4 s4 = *(const float4*)&sS[kk][v0];
            float kd0 = sKd[kk][lane*2], kd1 = sKd[kk][lane*2 + 1];
#pragma unroll
            for (int i = 0; i < 4; i++) {
                o[i][0] = fmaf(qr[i], s4.x, o[i][0]);
                o[i][1] = fmaf(qr[i], s4.y, o[i][1]);
                o[i][2] = fmaf(qr[i], s4.z, o[i][2]);
                o[i][3] = fmaf(qr[i], s4.w, o[i][3]);
                a2[i][0] = fmaf(qr[i], kd0, a2[i][0]);
                a2[i][1] = fmaf(qr[i], kd1, a2[i][1]);
            }
        }
        __syncthreads();
    }

    // causal mask + stash A
#pragma unroll
    for (int i = 0; i < 4; i++) {
        int tl = t0 + i;
        int tg = th * 32 + tl;
        int s0 = lane * 2;
        sA[tl][s0]     = (s0     <= tg) ? a2[i][0] : 0.f;
        sA[tl][s0 + 1] = (s0 + 1 <= tg) ? a2[i][1] : 0.f;
    }
    __syncthreads();

    // o_intra = A @ V (contraction over s = 64)
    for (int st = 0; st < 4; st++) {
#pragma unroll
        for (int u = 0; u < 2; u++) {
            int f  = tid + (u << 8);
            int sr = f >> 5;
            int sc = (f & 31) << 2;
            int r  = row_off(b, h, tchunk + st * 16 + sr) + sc;
            *(float4*)&sV[sr][sc] = *(const float4*)(g_v + r);
        }
        __syncthreads();
#pragma unroll
        for (int ss = 0; ss < 16; ss++) {
            int s = st * 16 + ss;
            float a[4];
#pragma unroll
            for (int i = 0; i < 4; i++) a[i] = sA[t0 + i][s];
            float4 v4 = *(const float4*)&sV[ss][v0];
#pragma unroll
            for (int i = 0; i < 4; i++) {
                o[i][0] = fmaf(a[i], v4.x, o[i][0]);
                o[i][1] = fmaf(a[i], v4.y, o[i][1]);
                o[i][2] = fmaf(a[i], v4.z, o[i][2]);
                o[i][3] = fmaf(a[i], v4.w, o[i][3]);
            }
        }
        __syncthreads();
    }

    // fused gated RMSNorm + bf16 hi/lo split write
    float4 w4 = *(const float4*)(g_norm_w + v0);
    float wr_[4] = {w4.x, w4.y, w4.z, w4.w};

#pragma unroll
    for (int i = 0; i < 4; i++) {
        float ss = 0.f;
#pragma unroll
        for (int j = 0; j < 4; j++) ss = fmaf(o[i][j], o[i][j], ss);
#pragma unroll
        for (int off = 16; off; off >>= 1)
            ss += __shfl_xor_sync(0xffffffffu, ss, off);
        float rms = rsqrtf(ss * (1.f / 128.f) + 1e-5f);

        int r = row_off(b, h, tbase + t0 + i);
        float4 g4 = *(const float4*)(g_g + r + v0);
        float gr[4] = {g4.x, g4.y, g4.z, g4.w};

        union { __nv_bfloat16 h[4]; uint2 u; } hh;
        union { __nv_bfloat16 h[4]; uint2 u; } ll;
#pragma unroll
        for (int j = 0; j < 4; j++) {
            float gvv = gr[j];
            float sw  = gvv / (1.f + __expf(-gvv));
            float on  = o[i][j] * rms * wr_[j] * sw;
            split_bf16(on, hh.h[j], ll.h[j]);
        }
        *(uint2*)&g_onhi[r + v0] = hh.u;
        *(uint2*)&g_onlo[r + v0] = ll.u;
    }
}

// ---------------------------------------------------------------------------
extern "C" void kernel_launch(void* const* d_in, const int* in_sizes, int n_in,
                              void* d_out, int out_size)
{
    const float* x        = (const float*)d_in[0];
    const float* Wq       = (const float*)d_in[1];
    const float* Wk       = (const float*)d_in[2];
    const float* Wv       = (const float*)d_in[3];
    const float* Wg       = (const float*)d_in[4];
    const float* Wgk1     = (const float*)d_in[5];
    const float* Wgk2     = (const float*)d_in[6];
    const float* bgk2     = (const float*)d_in[7];
    const float* g_norm_w = (const float*)d_in[8];
    const float* Wo       = (const float*)d_in[9];
    float* out = (float*)d_out;

    // Host-side attribute set; executed during capture, not a graph node.
    cudaFuncSetAttribute(gemm4_kernel,
        cudaFuncAttributeMaxDynamicSharedMemorySize, SMEM_GEMM4);
    cudaFuncSetAttribute(gemmo_kernel,
        cudaFuncAttributeMaxDynamicSharedMemorySize, SMEM_GEMMO);

    conv_w_kernel<<<dim3(32, 32, 5), dim3(256)>>>(Wq, Wk, Wv, Wg, Wo);
    conv_x_kernel<<<1024, 256>>>(x);
    lowrank_gk_kernel<<<64, 256>>>(x, Wgk1, Wgk2, bgk2);
    gemm4_kernel<<<dim3(16, 8, 4), 256, SMEM_GEMM4>>>();
    prep_kv_kernel<<<256, 512>>>();
    state_scan_kernel<<<256, 256>>>();
    chunk_out_kernel<<<256, 256>>>(g_norm_w);
    gemmo_kernel<<<dim3(32, 8), 256, SMEM_GEMMO>>>(out);
}